// round 16
// baseline (speedup 1.0000x reference)
#include <cuda_runtime.h>
#include <cuda_fp16.h>

#define NB 8
#define NC 12
#define GD 8
#define GH 16
#define GW 16
#define IH 1024
#define IW 1024

// Conflict-free fp16 line layout:
//   z-stride = 24 halfs = 48 B (12 used + 12 pad) -> z*3 granules mod 8 all distinct
//   x-stride = 200 halfs = 400 B
#define ZS 24
#define XS 200

__device__ __forceinline__ void ld6h2(const __half* p, __half2* h) {
    uint4 a = *reinterpret_cast<const uint4*>(p);
    uint2 b = *reinterpret_cast<const uint2*>(p + 8);
    h[0] = *reinterpret_cast<const __half2*>(&a.x);
    h[1] = *reinterpret_cast<const __half2*>(&a.y);
    h[2] = *reinterpret_cast<const __half2*>(&a.z);
    h[3] = *reinterpret_cast<const __half2*>(&a.w);
    h[4] = *reinterpret_cast<const __half2*>(&b.x);
    h[5] = *reinterpret_cast<const __half2*>(&b.y);
}

__global__ __launch_bounds__(512, 3) void slice_kernel(
    const float* __restrict__ grid_src,  // [n][c][z][y][x]
    const float* __restrict__ guide,     // [n][i][j]
    float* __restrict__ out)             // [n][c][i][j]
{
    __shared__ __align__(16) __half sm[GW * XS];   // 6400 B

    int bid = blockIdx.x;              // n*1024 + i
    int n = bid >> 10;
    int i = bid & 1023;
    int tid = threadIdx.x;

    // Guide prefetch: 2 consecutive pixels per thread (hidden under fill + sync)
    const float* grow = guide + (((size_t)n << 10) + i) * 1024;
    int j = tid << 1;
    float2 gv = *reinterpret_cast<const float2*>(grow + j);

    // ---- y-interp + fused transpose, vectorized ----
    float gy = ((float)i + 0.5f) * (16.0f / 1024.0f);
    float fy = floorf(gy - 0.5f);
    float wy1 = gy - 0.5f - fy;
    int iy = (int)fy;
    int y0 = max(0, min(GH - 1, iy));
    int y1 = max(0, min(GH - 1, iy + 1));

    __half2* smv = (__half2*)sm;       // x stride 100, z stride 12 (half2 units)

    if (tid < 192) {
        int c2 = tid / 32;
        int rem = tid & 31;
        int z = rem >> 2;
        int x4 = rem & 3;
        const float* p = grid_src
            + (((size_t)(n * NC + c2 * 2) * GD + z) * GH) * GW + x4 * 4;
        float4 a0 = __ldg((const float4*)(p + y0 * GW));
        float4 b0 = __ldg((const float4*)(p + y1 * GW));
        float4 a1 = __ldg((const float4*)(p + GD * GH * GW + y0 * GW));
        float4 b1 = __ldg((const float4*)(p + GD * GH * GW + y1 * GW));

        float e0 = fmaf(wy1, b0.x - a0.x, a0.x);
        float e1 = fmaf(wy1, b0.y - a0.y, a0.y);
        float e2 = fmaf(wy1, b0.z - a0.z, a0.z);
        float e3 = fmaf(wy1, b0.w - a0.w, a0.w);
        float o0 = fmaf(wy1, b1.x - a1.x, a1.x);
        float o1 = fmaf(wy1, b1.y - a1.y, a1.y);
        float o2 = fmaf(wy1, b1.z - a1.z, a1.z);
        float o3 = fmaf(wy1, b1.w - a1.w, a1.w);

        int base = z * 12 + c2;
        int xb = x4 * 4;
        smv[(xb + 0) * 100 + base] = __floats2half2_rn(e0, o0);
        smv[(xb + 1) * 100 + base] = __floats2half2_rn(e1, o1);
        smv[(xb + 2) * 100 + base] = __floats2half2_rn(e2, o2);
        smv[(xb + 3) * 100 + base] = __floats2half2_rn(e3, o3);
    }
    __syncthreads();

    size_t obase = (((size_t)(n * NC)) << 20) + ((size_t)i << 10);

    // ---- 2 consecutive pixels per thread, all-fp16 lerps ----
    __half2 res0[6], res1[6];

#pragma unroll
    for (int p = 0; p < 2; p++) {
        int jj = j + p;
        float g = p ? gv.y : gv.x;
        __half2* res = p ? res1 : res0;

        float gx = ((float)jj + 0.5f) * (16.0f / 1024.0f);
        float fx = floorf(gx - 0.5f);
        float wx1 = gx - 0.5f - fx;
        int ix = (int)fx;
        int x0 = max(0, min(GW - 1, ix));
        int x1 = max(0, min(GW - 1, ix + 1));

        float gz = g * 8.0f;
        float fz = floorf(gz - 0.5f);
        float wz1 = gz - 0.5f - fz;
        int iz = (int)fz;
        int z0 = max(0, min(GD - 1, iz));
        int z1 = max(0, min(GD - 1, iz + 1));

        __half2 wz = __float2half2_rn(wz1);
        __half2 wx = __float2half2_rn(wx1);

        const __half* A = sm + x0 * XS;
        const __half* B = sm + x1 * XS;

        // parallel 4-corner loads (max LDS MLP)
        __half2 hA0[6], hA1[6], hB0[6], hB1[6];
        ld6h2(A + z0 * ZS, hA0);
        ld6h2(A + z1 * ZS, hA1);
        ld6h2(B + z0 * ZS, hB0);
        ld6h2(B + z1 * ZS, hB1);

#pragma unroll
        for (int q = 0; q < 6; q++) {
            __half2 a = __hfma2(wz, __hsub2(hA1[q], hA0[q]), hA0[q]);
            __half2 b = __hfma2(wz, __hsub2(hB1[q], hB0[q]), hB0[q]);
            res[q] = __hfma2(wx, __hsub2(b, a), a);
        }
    }

#pragma unroll
    for (int q = 0; q < 6; q++) {
        float2 f0 = __half22float2(res0[q]);
        float2 f1 = __half22float2(res1[q]);
        size_t cbase = obase + (((size_t)(2 * q)) << 20) + (size_t)j;
        __stcs(reinterpret_cast<float2*>(out + cbase),
               make_float2(f0.x, f1.x));
        __stcs(reinterpret_cast<float2*>(out + cbase + (1u << 20)),
               make_float2(f0.y, f1.y));
    }
}

extern "C" void kernel_launch(void* const* d_in, const int* in_sizes, int n_in,
                              void* d_out, int out_size) {
    const float* grid_src = nullptr;
    const float* guide = nullptr;
    for (int k = 0; k < n_in; k++) {
        if (in_sizes[k] == NB * NC * GD * GH * GW) grid_src = (const float*)d_in[k];
        else if (in_sizes[k] == NB * IH * IW) guide = (const float*)d_in[k];
    }
    float* out = (float*)d_out;

    slice_kernel<<<NB * IH, 512>>>(grid_src, guide, out);
}

// round 17
// speedup vs baseline: 1.1259x; 1.1259x over previous
#include <cuda_runtime.h>
#include <cuda_fp16.h>

#define NB 8
#define NC 12
#define GD 8
#define GH 16
#define GW 16
#define IH 1024
#define IW 1024

// Conflict-free fp16 line layout:
//   z-stride = 24 halfs = 48 B (12 used + 12 pad) -> z*3 granules mod 8 all distinct
//   x-stride = 200 halfs = 400 B
#define ZS 24
#define XS 200

__device__ __forceinline__ void ld6h2(const __half* p, __half2* h) {
    uint4 a = *reinterpret_cast<const uint4*>(p);
    uint2 b = *reinterpret_cast<const uint2*>(p + 8);
    h[0] = *reinterpret_cast<const __half2*>(&a.x);
    h[1] = *reinterpret_cast<const __half2*>(&a.y);
    h[2] = *reinterpret_cast<const __half2*>(&a.z);
    h[3] = *reinterpret_cast<const __half2*>(&a.w);
    h[4] = *reinterpret_cast<const __half2*>(&b.x);
    h[5] = *reinterpret_cast<const __half2*>(&b.y);
}

__global__ __launch_bounds__(256, 5) void slice_kernel(
    const float* __restrict__ grid_src,  // [n][c][z][y][x]
    const float* __restrict__ guide,     // [n][i][j]
    float* __restrict__ out)             // [n][c][i][j]
{
    __shared__ __align__(16) __half sm[GW * XS];   // 6400 B

    int bid = blockIdx.x;              // n*1024 + i
    int n = bid >> 10;
    int i = bid & 1023;
    int tid = threadIdx.x;

    // Guide prefetch (hidden under fill + sync)
    const float* grow = guide + (((size_t)n << 10) + i) * 1024;
    int j0 = tid << 1;
    int j1 = j0 + 512;
    float2 gv0 = *reinterpret_cast<const float2*>(grow + j0);
    float2 gv1 = *reinterpret_cast<const float2*>(grow + j1);

    // ---- y-interp + fused transpose, vectorized ----
    float gy = ((float)i + 0.5f) * (16.0f / 1024.0f);
    float fy = floorf(gy - 0.5f);
    float wy1 = gy - 0.5f - fy;
    int iy = (int)fy;
    int y0 = max(0, min(GH - 1, iy));
    int y1 = max(0, min(GH - 1, iy + 1));

    __half2* smv = (__half2*)sm;       // x stride 100, z stride 12 (half2 units)

    if (tid < 192) {
        int c2 = tid / 32;
        int rem = tid & 31;
        int z = rem >> 2;
        int x4 = rem & 3;
        const float* p = grid_src
            + (((size_t)(n * NC + c2 * 2) * GD + z) * GH) * GW + x4 * 4;
        float4 a0 = __ldg((const float4*)(p + y0 * GW));
        float4 b0 = __ldg((const float4*)(p + y1 * GW));
        float4 a1 = __ldg((const float4*)(p + GD * GH * GW + y0 * GW));
        float4 b1 = __ldg((const float4*)(p + GD * GH * GW + y1 * GW));

        float e0 = fmaf(wy1, b0.x - a0.x, a0.x);
        float e1 = fmaf(wy1, b0.y - a0.y, a0.y);
        float e2 = fmaf(wy1, b0.z - a0.z, a0.z);
        float e3 = fmaf(wy1, b0.w - a0.w, a0.w);
        float o0 = fmaf(wy1, b1.x - a1.x, a1.x);
        float o1 = fmaf(wy1, b1.y - a1.y, a1.y);
        float o2 = fmaf(wy1, b1.z - a1.z, a1.z);
        float o3 = fmaf(wy1, b1.w - a1.w, a1.w);

        int base = z * 12 + c2;
        int xb = x4 * 4;
        smv[(xb + 0) * 100 + base] = __floats2half2_rn(e0, o0);
        smv[(xb + 1) * 100 + base] = __floats2half2_rn(e1, o1);
        smv[(xb + 2) * 100 + base] = __floats2half2_rn(e2, o2);
        smv[(xb + 3) * 100 + base] = __floats2half2_rn(e3, o3);
    }
    __syncthreads();

    size_t obase = (((size_t)(n * NC)) << 20) + ((size_t)i << 10);

    // ---- 4 pixels per thread: 2 groups of 2 consecutive j, all-fp16 lerps ----
#pragma unroll
    for (int gsel = 0; gsel < 2; gsel++) {
        int j = gsel ? j1 : j0;
        float2 gv = gsel ? gv1 : gv0;

        __half2 res0[6], res1[6];

#pragma unroll
        for (int p = 0; p < 2; p++) {
            int jj = j + p;
            float g = p ? gv.y : gv.x;
            __half2* res = p ? res1 : res0;

            float gx = ((float)jj + 0.5f) * (16.0f / 1024.0f);
            float fx = floorf(gx - 0.5f);
            float wx1 = gx - 0.5f - fx;
            int ix = (int)fx;
            int x0 = max(0, min(GW - 1, ix));
            int x1 = max(0, min(GW - 1, ix + 1));

            float gz = g * 8.0f;
            float fz = floorf(gz - 0.5f);
            float wz1 = gz - 0.5f - fz;
            int iz = (int)fz;
            int z0 = max(0, min(GD - 1, iz));
            int z1 = max(0, min(GD - 1, iz + 1));

            __half2 wz = __float2half2_rn(wz1);
            __half2 wx = __float2half2_rn(wx1);

            const __half* A = sm + x0 * XS;
            const __half* B = sm + x1 * XS;

            // parallel 4-corner loads (max LDS MLP)
            __half2 hA0[6], hA1[6], hB0[6], hB1[6];
            ld6h2(A + z0 * ZS, hA0);
            ld6h2(A + z1 * ZS, hA1);
            ld6h2(B + z0 * ZS, hB0);
            ld6h2(B + z1 * ZS, hB1);

#pragma unroll
            for (int q = 0; q < 6; q++) {
                __half2 a = __hfma2(wz, __hsub2(hA1[q], hA0[q]), hA0[q]);
                __half2 b = __hfma2(wz, __hsub2(hB1[q], hB0[q]), hB0[q]);
                res[q] = __hfma2(wx, __hsub2(b, a), a);
            }
        }

#pragma unroll
        for (int q = 0; q < 6; q++) {
            float2 f0 = __half22float2(res0[q]);
            float2 f1 = __half22float2(res1[q]);
            size_t cbase = obase + (((size_t)(2 * q)) << 20) + (size_t)j;
            __stcs(reinterpret_cast<float2*>(out + cbase),
                   make_float2(f0.x, f1.x));
            __stcs(reinterpret_cast<float2*>(out + cbase + (1u << 20)),
                   make_float2(f0.y, f1.y));
        }
    }
}

extern "C" void kernel_launch(void* const* d_in, const int* in_sizes, int n_in,
                              void* d_out, int out_size) {
    const float* grid_src = nullptr;
    const float* guide = nullptr;
    for (int k = 0; k < n_in; k++) {
        if (in_sizes[k] == NB * NC * GD * GH * GW) grid_src = (const float*)d_in[k];
        else if (in_sizes[k] == NB * IH * IW) guide = (const float*)d_in[k];
    }
    float* out = (float*)d_out;

    slice_kernel<<<NB * IH, 256>>>(grid_src, guide, out);
}